// round 5
// baseline (speedup 1.0000x reference)
#include <cuda_runtime.h>
#include <cstdint>
#include <cfloat>

// IBQ VQ: tf32 mma.sync pass with self-certification + exact-fp32 rescue of near-tie rows.
//   d[b,n] = (sz[b]+se[n]) - 2*dot(z[b],e[n]);  idx=argmin (first index on ties)
// Pass 1 (tf32 3-term MMA) flags rows whose argmin could depend on fp32 rounding order.
// Rescue recomputes flagged rows with R1-proven numerics (sequential fp32 FMA chain).

#define DIM      256
#define TM       128
#define TN       128
#define CHUNK_K  32
#define NSTAGE   3
#define THREADS  256
#define MAX_B    32768
#define MAX_NE   8192
#define THR      1.5e-6f

__device__ float g_sz[MAX_B];
__device__ float g_se[MAX_NE];
__device__ float g_zhi[MAX_B * DIM];
__device__ float g_zlo[MAX_B * DIM];
__device__ float g_ehi[MAX_NE * DIM];
__device__ float g_elo[MAX_NE * DIM];
__device__ int   g_idx[MAX_B];
__device__ int   g_flag[MAX_B];
__device__ int   g_list[MAX_B];
__device__ int   g_cnt;

#define STG_BYTES   65536
#define OFF_SE      (3 * STG_BYTES)
#define OFF_RED_D   (OFF_SE + 512)
#define OFF_RED_P   (OFF_RED_D + 512)
#define SMEM_REQ    (OFF_RED_P + 512)

__device__ __forceinline__ uint32_t smem_u32(const void* p) {
    uint32_t a;
    asm("{ .reg .u64 t; cvta.to.shared.u64 t, %1; cvt.u32.u64 %0, t; }" : "=r"(a) : "l"(p));
    return a;
}
__device__ __forceinline__ uint32_t f2tf32(float v) {
    uint32_t u; asm("cvt.rna.tf32.f32 %0, %1;" : "=r"(u) : "f"(v)); return u;
}
__device__ __forceinline__ void cp16(uint32_t s, const void* g) {
    asm volatile("cp.async.cg.shared.global [%0], [%1], 16;" :: "r"(s), "l"(g));
}
#define CP_COMMIT() asm volatile("cp.async.commit_group;" ::: "memory")
#define CP_WAIT2()  asm volatile("cp.async.wait_group 2;" ::: "memory")
#define CP_WAIT0()  asm volatile("cp.async.wait_group 0;" ::: "memory")

#define LDSM4(r, a) \
    asm volatile("ldmatrix.sync.aligned.m8n8.x4.shared.b16 {%0,%1,%2,%3}, [%4];" \
                 : "=r"((r)[0]), "=r"((r)[1]), "=r"((r)[2]), "=r"((r)[3]) : "r"(a))

#define MMA(d, a, b0, b1) \
    asm volatile("mma.sync.aligned.m16n8k8.row.col.f32.tf32.tf32.f32 " \
                 "{%0,%1,%2,%3}, {%4,%5,%6,%7}, {%8,%9}, {%0,%1,%2,%3};" \
                 : "+f"((d)[0]), "+f"((d)[1]), "+f"((d)[2]), "+f"((d)[3]) \
                 : "r"((a)[0]), "r"((a)[1]), "r"((a)[2]), "r"((a)[3]), "r"(b0), "r"(b1))

__device__ __forceinline__ uint32_t swz(int row, int g) {
    return (uint32_t)(row * 128 + ((g ^ (row & 7)) << 4));
}
__device__ __forceinline__ float ulp_of(float d) {
    return __uint_as_float(__float_as_uint(d) & 0xFF800000u) * 1.1920929e-7f;
}

// argmin state with certification
struct AMin { float d0; int n0; bool nm0; bool flag; };

__device__ __forceinline__ void amin_update(AMin& s, float d, int n, bool nm) {
    bool better = (d < s.d0) || (d == s.d0 && n < s.n0);
    float dmin = better ? d : s.d0;
    float dmax = better ? s.d0 : d;
    bool close = (dmax - dmin) <= 2.125f * ulp_of(dmin);
    if (close) s.flag |= (nm || s.nm0);
    if (better) { s.d0 = d; s.n0 = n; s.nm0 = nm; }
}

// ---------------- prep kernels ----------------
__global__ void row_sumsq_kernel(const float* __restrict__ x, float* __restrict__ o, int rows) {
    int w = (int)((blockIdx.x * blockDim.x + threadIdx.x) >> 5);
    int lane = threadIdx.x & 31;
    if (w >= rows) return;
    const float4* r = (const float4*)(x + (size_t)w * DIM);
    float4 v0 = r[lane * 2];
    float4 v1 = r[lane * 2 + 1];
    float s = v0.x * v0.x;
    s += v0.y * v0.y; s += v0.z * v0.z; s += v0.w * v0.w;
    s += v1.x * v1.x; s += v1.y * v1.y; s += v1.z * v1.z; s += v1.w * v1.w;
#pragma unroll
    for (int off = 16; off; off >>= 1) s += __shfl_xor_sync(0xffffffffu, s, off);
    if (lane == 0) o[w] = s;
}

__global__ void split_tf32_kernel(const float* __restrict__ x, float* __restrict__ hi,
                                  float* __restrict__ lo, int n4) {
    int i = blockIdx.x * blockDim.x + threadIdx.x;
    if (i >= n4) return;
    float4 v = ((const float4*)x)[i];
    float4 h, l;
    h.x = __uint_as_float(f2tf32(v.x)); l.x = __uint_as_float(f2tf32(v.x - h.x));
    h.y = __uint_as_float(f2tf32(v.y)); l.y = __uint_as_float(f2tf32(v.y - h.y));
    h.z = __uint_as_float(f2tf32(v.z)); l.z = __uint_as_float(f2tf32(v.z - h.z));
    h.w = __uint_as_float(f2tf32(v.w)); l.w = __uint_as_float(f2tf32(v.w - h.w));
    ((float4*)hi)[i] = h;
    ((float4*)lo)[i] = l;
}

// ---------------- pass 1: tf32 MMA + certification ----------------
__global__ void __launch_bounds__(THREADS, 1)
vq_mma_kernel(const float* __restrict__ zhi, const float* __restrict__ zlo,
              const float* __restrict__ ehi, const float* __restrict__ elo,
              const float* __restrict__ sz, const float* __restrict__ se, int NE)
{
    extern __shared__ char sp[];
    const uint32_t sb = smem_u32(sp);

    const int tid  = threadIdx.x;
    const int lane = tid & 31;
    const int wid  = tid >> 5;
    const int wm   = (wid & 3) * 32;
    const int wn   = (wid >> 2) * 64;
    const int bbase = blockIdx.x * TM;
    const int NTILE = NE / TN;
    const int NCHK  = NTILE * 8;

    const int lrowA = lane & 15;
    const int gselA = lane >> 4;
    const int lrowB = (lane & 7) + ((lane >> 4) << 3);
    const int gselB = (lane >> 3) & 1;

    AMin st[4];
#pragma unroll
    for (int s = 0; s < 4; s++) st[s] = {FLT_MAX, 0, false, false};

    float szr[4];
#pragma unroll
    for (int s = 0; s < 4; s++)
        szr[s] = __ldg(sz + bbase + wm + (s >> 1) * 16 + (s & 1) * 8 + (lane >> 2));

    float acc[2][8][4];
#pragma unroll
    for (int mt = 0; mt < 2; mt++)
#pragma unroll
        for (int nt = 0; nt < 8; nt++)
#pragma unroll
            for (int k = 0; k < 4; k++) acc[mt][nt][k] = 0.0f;

    auto issue_chunk = [&](int i, int stage) {
        int c = i & 7, t = i >> 3;
        uint32_t sA = sb + stage * STG_BYTES;
        const float* gAh = zhi + (size_t)bbase * DIM + c * CHUNK_K;
        const float* gAl = zlo + (size_t)bbase * DIM + c * CHUNK_K;
        const float* gBh = ehi + (size_t)t * TN * DIM + c * CHUNK_K;
        const float* gBl = elo + (size_t)t * TN * DIM + c * CHUNK_K;
#pragma unroll
        for (int it = 0; it < 4; it++) {
            int idx = tid + it * 256;
            int row = idx >> 3, g = idx & 7;
            uint32_t so = swz(row, g);
            size_t go = (size_t)row * DIM + g * 4;
            cp16(sA + so,         gAh + go);
            cp16(sA + 16384 + so, gAl + go);
            cp16(sA + 32768 + so, gBh + go);
            cp16(sA + 49152 + so, gBl + go);
        }
        CP_COMMIT();
    };

    issue_chunk(0, 0);
    issue_chunk(1, 1);
    issue_chunk(2, 2);

    float* sm_se = (float*)(sp + OFF_SE);

#pragma unroll 1
    for (int i = 0; i < NCHK; i++) {
        int stage = i % NSTAGE;
        CP_WAIT2();
        __syncthreads();

        if ((i & 7) == 0 && tid < 32)
            ((float4*)sm_se)[tid] = ((const float4*)(se + (i >> 3) * TN))[tid];

        uint32_t base = sb + stage * STG_BYTES;
#pragma unroll
        for (int ks = 0; ks < 4; ks++) {
            uint32_t ah[2][4], al[2][4], bh[4][4], bl[4][4];
#pragma unroll
            for (int mt = 0; mt < 2; mt++) {
                int row = wm + mt * 16 + lrowA;
                int g = ks * 2 + gselA;
                uint32_t ad = base + swz(row, g);
                LDSM4(ah[mt], ad);
                LDSM4(al[mt], ad + 16384);
            }
#pragma unroll
            for (int p = 0; p < 4; p++) {
                int row = wn + p * 16 + lrowB;
                int g = ks * 2 + gselB;
                uint32_t ad = base + 32768 + swz(row, g);
                LDSM4(bh[p], ad);
                LDSM4(bl[p], ad + 16384);
            }
#pragma unroll
            for (int mt = 0; mt < 2; mt++)
#pragma unroll
                for (int nt = 0; nt < 8; nt++) {
                    int p = nt >> 1, o = (nt & 1) * 2;
                    MMA(acc[mt][nt], ah[mt], bh[p][o], bh[p][o + 1]);
                    MMA(acc[mt][nt], al[mt], bh[p][o], bh[p][o + 1]);
                    MMA(acc[mt][nt], ah[mt], bl[p][o], bl[p][o + 1]);
                }
        }

        if ((i & 7) == 7) {
            int t = i >> 3;
#pragma unroll
            for (int mt = 0; mt < 2; mt++)
#pragma unroll
                for (int half = 0; half < 2; half++) {
                    int slot = mt * 2 + half;
                    float szv = szr[slot];
#pragma unroll
                    for (int nt = 0; nt < 8; nt++)
#pragma unroll
                        for (int j = 0; j < 2; j++) {
                            float p = acc[mt][nt][half * 2 + j];
                            int nl = wn + nt * 8 + (lane & 3) * 2 + j;
                            float tt = __fadd_rn(szv, sm_se[nl]);
                            float q  = __fmul_rn(-2.0f, p);
                            float d  = __fadd_rn(tt, q);
                            float zzv = __fadd_rn(d, -tt);   // exact (Fast2Sum)
                            float r   = __fadd_rn(q, -zzv);  // exact residual
                            float ue  = ulp_of(d);
                            bool nm = fabsf(r) >= (0.5f * ue - THR);
                            amin_update(st[slot], d, t * TN + nl, nm);
                        }
                }
#pragma unroll
            for (int mt = 0; mt < 2; mt++)
#pragma unroll
                for (int nt = 0; nt < 8; nt++)
#pragma unroll
                    for (int k = 0; k < 4; k++) acc[mt][nt][k] = 0.0f;
        }

        __syncthreads();
        if (i + NSTAGE < NCHK) issue_chunk(i + NSTAGE, stage);
    }
    CP_WAIT0();

    // quad-lane merge (lanes xor 1,2 share a row)
#pragma unroll
    for (int s = 0; s < 4; s++) {
#pragma unroll
        for (int off = 1; off <= 2; off <<= 1) {
            uint32_t pk = (uint32_t)st[s].n0 | (st[s].nm0 ? 0x40000000u : 0u)
                                             | (st[s].flag ? 0x80000000u : 0u);
            float od = __shfl_xor_sync(0xffffffffu, st[s].d0, off);
            uint32_t opk = __shfl_xor_sync(0xffffffffu, pk, off);
            int on = (int)(opk & 0x3FFFFFFFu);
            bool onm = (opk >> 30) & 1, ofl = (opk >> 31) & 1;
            st[s].flag |= ofl;
            amin_update(st[s], od, on, onm);
        }
    }

    float* sd = (float*)(sp + OFF_RED_D);
    uint32_t* spk = (uint32_t*)(sp + OFF_RED_P);
    if (wn == 0 && (lane & 3) == 0) {
#pragma unroll
        for (int s = 0; s < 4; s++) {
            int row = wm + (s >> 1) * 16 + (s & 1) * 8 + (lane >> 2);
            sd[row] = st[s].d0;
            spk[row] = (uint32_t)st[s].n0 | (st[s].nm0 ? 0x40000000u : 0u)
                                          | (st[s].flag ? 0x80000000u : 0u);
        }
    }
    __syncthreads();
    if (wn != 0 && (lane & 3) == 0) {
#pragma unroll
        for (int s = 0; s < 4; s++) {
            int row = wm + (s >> 1) * 16 + (s & 1) * 8 + (lane >> 2);
            float od = sd[row];
            uint32_t opk = spk[row];
            int on = (int)(opk & 0x3FFFFFFFu);
            bool onm = (opk >> 30) & 1, ofl = (opk >> 31) & 1;
            st[s].flag |= ofl;
            amin_update(st[s], od, on, onm);
            g_idx[bbase + row] = st[s].n0;
            g_flag[bbase + row] = st[s].flag ? 1 : 0;
        }
    }
}

// ---------------- compaction ----------------
__global__ void zero_cnt_kernel() { g_cnt = 0; }

__global__ void compact_kernel(int B) {
    int i = blockIdx.x * blockDim.x + threadIdx.x;
    if (i < B && g_flag[i]) {
        int p = atomicAdd(&g_cnt, 1);
        g_list[p] = i;
    }
}

// ---------------- rescue: exact fp32 (R1 numerics) for flagged rows ----------------
__global__ void __launch_bounds__(256, 1)
rescue_kernel(const float* __restrict__ z, const float* __restrict__ emb,
              const float* __restrict__ sz, const float* __restrict__ se, int NE)
{
    __shared__ float smz[16][DIM];
    __shared__ float rd[16][16];
    __shared__ int   rn_[16][16];

    const int tid = threadIdx.x;
    const int r = tid >> 4;       // row slot 0..15
    const int c = tid & 15;       // col group 0..15
    const int cnt = g_cnt;

    for (int tile = blockIdx.x; tile * 16 < cnt; tile += gridDim.x) {
        int li = tile * 16 + r;
        int grow = (li < cnt) ? g_list[li] : g_list[tile * 16];

        // load 16 z rows
        {
            const float4* src = (const float4*)(z + (size_t)grow * DIM);
            float4* dst = (float4*)smz[r];
#pragma unroll
            for (int q = 0; q < 4; q++) dst[c * 4 + q] = src[c * 4 + q];
        }
        __syncthreads();

        float szv = __ldg(sz + grow);
        float bd = FLT_MAX; int bn = 0;

#pragma unroll 1
        for (int pass = 0; pass < NE / 128; pass++) {
            int nb = pass * 128 + c * 8;
            float acc[8] = {0, 0, 0, 0, 0, 0, 0, 0};
#pragma unroll 4
            for (int k4 = 0; k4 < DIM / 4; k4++) {
                float a0 = smz[r][k4 * 4 + 0];
                float a1 = smz[r][k4 * 4 + 1];
                float a2 = smz[r][k4 * 4 + 2];
                float a3 = smz[r][k4 * 4 + 3];
#pragma unroll
                for (int j = 0; j < 8; j++) {
                    float4 b = __ldg((const float4*)(emb + (size_t)(nb + j) * DIM + k4 * 4));
                    acc[j] = __fmaf_rn(a0, b.x, acc[j]);
                    acc[j] = __fmaf_rn(a1, b.y, acc[j]);
                    acc[j] = __fmaf_rn(a2, b.z, acc[j]);
                    acc[j] = __fmaf_rn(a3, b.w, acc[j]);
                }
            }
#pragma unroll
            for (int j = 0; j < 8; j++) {
                float tt = __fadd_rn(szv, __ldg(se + nb + j));
                float d = __fadd_rn(tt, __fmul_rn(-2.0f, acc[j]));
                int n = nb + j;
                if (d < bd || (d == bd && n < bn)) { bd = d; bn = n; }
            }
        }

        rd[r][c] = bd; rn_[r][c] = bn;
        __syncthreads();
        if (c == 0 && li < cnt) {
            float fd = rd[r][0]; int fn = rn_[r][0];
#pragma unroll
            for (int q = 1; q < 16; q++) {
                float od = rd[r][q]; int on = rn_[r][q];
                if (od < fd || (od == fd && on < fn)) { fd = od; fn = on; }
            }
            g_idx[grow] = fn;
        }
        __syncthreads();
    }
}

// ---------------- output gather ----------------
__global__ void gather_kernel(const float* __restrict__ emb, float* __restrict__ outp,
                              int B, int mode, long long idx_off)
{
    int w = (int)((blockIdx.x * blockDim.x + threadIdx.x) >> 5);
    int lane = threadIdx.x & 31;
    if (w >= B) return;
    int idx = g_idx[w];
    if (mode & 1) {
        const float4* src = (const float4*)(emb + (size_t)idx * DIM);
        float4* dst = (float4*)(outp + (size_t)w * DIM);
        dst[lane] = src[lane];
        dst[lane + 32] = src[lane + 32];
    }
    if ((mode & 2) && lane == 0) outp[idx_off + w] = (float)idx;
}

extern "C" void kernel_launch(void* const* d_in, const int* in_sizes, int n_in,
                              void* d_out, int out_size) {
    const float* z   = (const float*)d_in[0];
    const float* emb = (const float*)d_in[1];
    float* outp = (float*)d_out;

    int B  = in_sizes[0] / DIM;
    int NE = in_sizes[1] / DIM;

    float *sz_p, *se_p, *zhi_p, *zlo_p, *ehi_p, *elo_p;
    cudaGetSymbolAddress((void**)&sz_p,  g_sz);
    cudaGetSymbolAddress((void**)&se_p,  g_se);
    cudaGetSymbolAddress((void**)&zhi_p, g_zhi);
    cudaGetSymbolAddress((void**)&zlo_p, g_zlo);
    cudaGetSymbolAddress((void**)&ehi_p, g_ehi);
    cudaGetSymbolAddress((void**)&elo_p, g_elo);

    row_sumsq_kernel<<<(B + 7) / 8, 256>>>(z, sz_p, B);
    row_sumsq_kernel<<<(NE + 7) / 8, 256>>>(emb, se_p, NE);
    int nz4 = B * DIM / 4, ne4 = NE * DIM / 4;
    split_tf32_kernel<<<(nz4 + 255) / 256, 256>>>(z, zhi_p, zlo_p, nz4);
    split_tf32_kernel<<<(ne4 + 255) / 256, 256>>>(emb, ehi_p, elo_p, ne4);

    zero_cnt_kernel<<<1, 1>>>();

    cudaFuncSetAttribute(vq_mma_kernel, cudaFuncAttributeMaxDynamicSharedMemorySize, SMEM_REQ);
    vq_mma_kernel<<<B / TM, THREADS, SMEM_REQ>>>(zhi_p, zlo_p, ehi_p, elo_p, sz_p, se_p, NE);

    compact_kernel<<<(B + 255) / 256, 256>>>(B);
    rescue_kernel<<<256, 256>>>(z, emb, sz_p, se_p, NE);

    long long zq_elems = (long long)B * DIM;
    int mode; long long idx_off;
    if ((long long)out_size >= zq_elems + B) { mode = 3; idx_off = zq_elems; }
    else if ((long long)out_size >= zq_elems) { mode = 1; idx_off = 0; }
    else { mode = 2; idx_off = 0; }

    gather_kernel<<<(B * 32 + 255) / 256, 256>>>(emb, outp, B, mode, idx_off);
}

// round 6
// speedup vs baseline: 12.8029x; 12.8029x over previous
#include <cuda_runtime.h>
#include <cstdint>
#include <cfloat>

// IBQ VQ: tf32 mma.sync pass + soundness certification + R1-numerics tiled rescue.
//   d[b,n] = (sz[b]+se[n]) - 2*dot(z[b],e[n]);  idx=argmin (first index on ties)
// Ground truth (empirically == reference on all rows, R5): sequential-k fp32 FMA chain,
// d = fadd(fadd(sz,se), fmul(-2,p)). MMA pass flags rows where its answer could differ;
// flagged rows are recomputed with exactly the ground-truth numerics.

#define DIM      256
#define TM       128
#define TN       128
#define NSTAGE   3
#define THREADS  256
#define MAX_B    32768
#define MAX_NE   8192
#define THR      5e-7f
#define WINDOW   2.125f

__device__ float g_sz[MAX_B];
__device__ float g_se[MAX_NE];
__device__ float g_zhi[MAX_B * DIM];
__device__ float g_zlo[MAX_B * DIM];
__device__ float g_ehi[MAX_NE * DIM];
__device__ float g_elo[MAX_NE * DIM];
__device__ int   g_idx[MAX_B];
__device__ int   g_flag[MAX_B];
__device__ int   g_list[MAX_B];
__device__ int   g_cnt;

#define STG_BYTES   65536
#define OFF_SE      (3 * STG_BYTES)
#define OFF_RED_D   (OFF_SE + 512)
#define OFF_RED_N   (OFF_RED_D + 512)
#define OFF_RED_M   (OFF_RED_N + 512)
#define SMEM_REQ    (OFF_RED_M + 512)

__device__ __forceinline__ uint32_t smem_u32(const void* p) {
    uint32_t a;
    asm("{ .reg .u64 t; cvta.to.shared.u64 t, %1; cvt.u32.u64 %0, t; }" : "=r"(a) : "l"(p));
    return a;
}
__device__ __forceinline__ uint32_t f2tf32(float v) {
    uint32_t u; asm("cvt.rna.tf32.f32 %0, %1;" : "=r"(u) : "f"(v)); return u;
}
__device__ __forceinline__ void cp16(uint32_t s, const void* g) {
    asm volatile("cp.async.cg.shared.global [%0], [%1], 16;" :: "r"(s), "l"(g));
}
#define CP_COMMIT() asm volatile("cp.async.commit_group;" ::: "memory")
#define CP_WAIT2()  asm volatile("cp.async.wait_group 2;" ::: "memory")
#define CP_WAIT0()  asm volatile("cp.async.wait_group 0;" ::: "memory")

#define LDSM4(r, a) \
    asm volatile("ldmatrix.sync.aligned.m8n8.x4.shared.b16 {%0,%1,%2,%3}, [%4];" \
                 : "=r"((r)[0]), "=r"((r)[1]), "=r"((r)[2]), "=r"((r)[3]) : "r"(a))

#define MMA(d, a, b0, b1) \
    asm volatile("mma.sync.aligned.m16n8k8.row.col.f32.tf32.tf32.f32 " \
                 "{%0,%1,%2,%3}, {%4,%5,%6,%7}, {%8,%9}, {%0,%1,%2,%3};" \
                 : "+f"((d)[0]), "+f"((d)[1]), "+f"((d)[2]), "+f"((d)[3]) \
                 : "r"((a)[0]), "r"((a)[1]), "r"((a)[2]), "r"((a)[3]), "r"(b0), "r"(b1))

__device__ __forceinline__ uint32_t swz(int row, int g) {
    return (uint32_t)(row * 128 + ((g ^ (row & 7)) << 4));
}
__device__ __forceinline__ float ulp_of(float d) {
    return __uint_as_float(__float_as_uint(d) & 0xFF800000u) * 1.1920929e-7f;
}

typedef unsigned long long ull;
#define PACK2(d, x, y) \
    asm("mov.b64 %0, {%1, %2};" : "=l"(d) : "r"(__float_as_uint(x)), "r"(__float_as_uint(y)))
#define FMA2(acc, a, b) \
    asm("fma.rn.f32x2 %0, %1, %2, %3;" : "=l"(acc) : "l"(a), "l"(b), "l"(acc))
#define UNPACK2(x, y, d) \
    asm("mov.b64 {%0, %1}, %2;" : "=r"(x), "=r"(y) : "l"(d))

// ---------------- prep kernels ----------------
__global__ void row_sumsq_kernel(const float* __restrict__ x, float* __restrict__ o, int rows) {
    int w = (int)((blockIdx.x * blockDim.x + threadIdx.x) >> 5);
    int lane = threadIdx.x & 31;
    if (w >= rows) return;
    const float4* r = (const float4*)(x + (size_t)w * DIM);
    float4 v0 = r[lane * 2];
    float4 v1 = r[lane * 2 + 1];
    float s = v0.x * v0.x;
    s += v0.y * v0.y; s += v0.z * v0.z; s += v0.w * v0.w;
    s += v1.x * v1.x; s += v1.y * v1.y; s += v1.z * v1.z; s += v1.w * v1.w;
#pragma unroll
    for (int off = 16; off; off >>= 1) s += __shfl_xor_sync(0xffffffffu, s, off);
    if (lane == 0) o[w] = s;
}

__global__ void split_tf32_kernel(const float* __restrict__ x, float* __restrict__ hi,
                                  float* __restrict__ lo, int n4) {
    int i = blockIdx.x * blockDim.x + threadIdx.x;
    if (i >= n4) return;
    float4 v = ((const float4*)x)[i];
    float4 h, l;
    h.x = __uint_as_float(f2tf32(v.x)); l.x = __uint_as_float(f2tf32(v.x - h.x));
    h.y = __uint_as_float(f2tf32(v.y)); l.y = __uint_as_float(f2tf32(v.y - h.y));
    h.z = __uint_as_float(f2tf32(v.z)); l.z = __uint_as_float(f2tf32(v.z - h.z));
    h.w = __uint_as_float(f2tf32(v.w)); l.w = __uint_as_float(f2tf32(v.w - h.w));
    ((float4*)hi)[i] = h;
    ((float4*)lo)[i] = l;
}

// ---------------- pass 1: tf32 MMA + certification ----------------
__global__ void __launch_bounds__(THREADS, 1)
vq_mma_kernel(const float* __restrict__ zhi, const float* __restrict__ zlo,
              const float* __restrict__ ehi, const float* __restrict__ elo,
              const float* __restrict__ sz, const float* __restrict__ se, int NE)
{
    extern __shared__ char sp[];
    const uint32_t sb = smem_u32(sp);

    const int tid  = threadIdx.x;
    const int lane = tid & 31;
    const int wid  = tid >> 5;
    const int wm   = (wid & 3) * 32;
    const int wn   = (wid >> 2) * 64;
    const int bbase = blockIdx.x * TM;
    const int NTILE = NE / TN;
    const int NCHK  = NTILE * 8;

    const int lrowA = lane & 15;
    const int gselA = lane >> 4;
    const int lrowB = (lane & 7) + ((lane >> 4) << 3);
    const int gselB = (lane >> 3) & 1;

    // per-slot state: winner (d1,n1) + min d over midpoint-near candidates
    float d1[4] = {FLT_MAX, FLT_MAX, FLT_MAX, FLT_MAX};
    int   n1[4] = {0, 0, 0, 0};
    float dnm[4] = {FLT_MAX, FLT_MAX, FLT_MAX, FLT_MAX};

    float szr[4];
#pragma unroll
    for (int s = 0; s < 4; s++)
        szr[s] = __ldg(sz + bbase + wm + (s >> 1) * 16 + (s & 1) * 8 + (lane >> 2));

    float acc[2][8][4];
#pragma unroll
    for (int mt = 0; mt < 2; mt++)
#pragma unroll
        for (int nt = 0; nt < 8; nt++)
#pragma unroll
            for (int k = 0; k < 4; k++) acc[mt][nt][k] = 0.0f;

    auto issue_chunk = [&](int i, int stage) {
        int c = i & 7, t = i >> 3;
        uint32_t sA = sb + stage * STG_BYTES;
        const float* gAh = zhi + (size_t)bbase * DIM + c * 32;
        const float* gAl = zlo + (size_t)bbase * DIM + c * 32;
        const float* gBh = ehi + (size_t)t * TN * DIM + c * 32;
        const float* gBl = elo + (size_t)t * TN * DIM + c * 32;
#pragma unroll
        for (int it = 0; it < 4; it++) {
            int idx = tid + it * 256;
            int row = idx >> 3, g = idx & 7;
            uint32_t so = swz(row, g);
            size_t go = (size_t)row * DIM + g * 4;
            cp16(sA + so,         gAh + go);
            cp16(sA + 16384 + so, gAl + go);
            cp16(sA + 32768 + so, gBh + go);
            cp16(sA + 49152 + so, gBl + go);
        }
        CP_COMMIT();
    };

    issue_chunk(0, 0);
    issue_chunk(1, 1);
    issue_chunk(2, 2);

    float* sm_se = (float*)(sp + OFF_SE);

#pragma unroll 1
    for (int i = 0; i < NCHK; i++) {
        int stage = i % NSTAGE;
        CP_WAIT2();
        __syncthreads();

        if ((i & 7) == 0 && tid < 32)
            ((float4*)sm_se)[tid] = ((const float4*)(se + (i >> 3) * TN))[tid];

        uint32_t base = sb + stage * STG_BYTES;
#pragma unroll
        for (int ks = 0; ks < 4; ks++) {
            uint32_t ah[2][4], al[2][4], bh[4][4], bl[4][4];
#pragma unroll
            for (int mt = 0; mt < 2; mt++) {
                int row = wm + mt * 16 + lrowA;
                int g = ks * 2 + gselA;
                uint32_t ad = base + swz(row, g);
                LDSM4(ah[mt], ad);
                LDSM4(al[mt], ad + 16384);
            }
#pragma unroll
            for (int p = 0; p < 4; p++) {
                int row = wn + p * 16 + lrowB;
                int g = ks * 2 + gselB;
                uint32_t ad = base + 32768 + swz(row, g);
                LDSM4(bh[p], ad);
                LDSM4(bl[p], ad + 16384);
            }
#pragma unroll
            for (int mt = 0; mt < 2; mt++)
#pragma unroll
                for (int nt = 0; nt < 8; nt++) {
                    int p = nt >> 1, o = (nt & 1) * 2;
                    MMA(acc[mt][nt], ah[mt], bh[p][o], bh[p][o + 1]);
                    MMA(acc[mt][nt], al[mt], bh[p][o], bh[p][o + 1]);
                    MMA(acc[mt][nt], ah[mt], bl[p][o], bl[p][o + 1]);
                }
        }

        if ((i & 7) == 7) {
            int t = i >> 3;
#pragma unroll
            for (int mt = 0; mt < 2; mt++)
#pragma unroll
                for (int half = 0; half < 2; half++) {
                    int slot = mt * 2 + half;
                    float szv = szr[slot];
#pragma unroll
                    for (int nt = 0; nt < 8; nt++)
#pragma unroll
                        for (int j = 0; j < 2; j++) {
                            float p = acc[mt][nt][half * 2 + j];
                            int nl = wn + nt * 8 + (lane & 3) * 2 + j;
                            float tt = __fadd_rn(szv, sm_se[nl]);
                            float q  = __fmul_rn(-2.0f, p);
                            float d  = __fadd_rn(tt, q);
                            float zzv = __fadd_rn(d, -tt);   // exact (Fast2Sum)
                            float r   = __fadd_rn(q, -zzv);  // exact rounding residual
                            bool nm = fabsf(r) >= (0.5f * ulp_of(d) - THR);
                            if (nm && d < dnm[slot]) dnm[slot] = d;
                            int ng = t * TN + nl;
                            if (d < d1[slot]) { d1[slot] = d; n1[slot] = ng; }
                        }
                }
#pragma unroll
            for (int mt = 0; mt < 2; mt++)
#pragma unroll
                for (int nt = 0; nt < 8; nt++)
#pragma unroll
                    for (int k = 0; k < 4; k++) acc[mt][nt][k] = 0.0f;
        }

        __syncthreads();
        if (i + NSTAGE < NCHK) issue_chunk(i + NSTAGE, stage);
    }
    CP_WAIT0();

    // quad-lane merge (lanes xor 1,2 share a row); n increases with lane so
    // (od==d, on) with on<n only if od from lower-n candidate — keep lexicographic.
#pragma unroll
    for (int s = 0; s < 4; s++) {
#pragma unroll
        for (int off = 1; off <= 2; off <<= 1) {
            float od = __shfl_xor_sync(0xffffffffu, d1[s], off);
            int   on = __shfl_xor_sync(0xffffffffu, n1[s], off);
            float om = __shfl_xor_sync(0xffffffffu, dnm[s], off);
            if (od < d1[s] || (od == d1[s] && on < n1[s])) { d1[s] = od; n1[s] = on; }
            if (om < dnm[s]) dnm[s] = om;
        }
    }

    float* sd = (float*)(sp + OFF_RED_D);
    int*   sn = (int*)(sp + OFF_RED_N);
    float* sm = (float*)(sp + OFF_RED_M);
    if (wn == 0 && (lane & 3) == 0) {
#pragma unroll
        for (int s = 0; s < 4; s++) {
            int row = wm + (s >> 1) * 16 + (s & 1) * 8 + (lane >> 2);
            sd[row] = d1[s]; sn[row] = n1[s]; sm[row] = dnm[s];
        }
    }
    __syncthreads();
    if (wn != 0 && (lane & 3) == 0) {
#pragma unroll
        for (int s = 0; s < 4; s++) {
            int row = wm + (s >> 1) * 16 + (s & 1) * 8 + (lane >> 2);
            float od = sd[row]; int on = sn[row]; float om = sm[row];
            if (od < d1[s] || (od == d1[s] && on < n1[s])) { d1[s] = od; n1[s] = on; }
            if (om < dnm[s]) dnm[s] = om;
            g_idx[bbase + row] = n1[s];
            g_flag[bbase + row] = (dnm[s] <= d1[s] + WINDOW * ulp_of(d1[s])) ? 1 : 0;
        }
    }
}

// ---------------- compaction ----------------
__global__ void zero_cnt_kernel() { g_cnt = 0; }

__global__ void compact_kernel(int B) {
    int i = blockIdx.x * blockDim.x + threadIdx.x;
    if (i < B && g_flag[i]) {
        int p = atomicAdd(&g_cnt, 1);
        g_list[p] = i;
    }
}

// ---------------- rescue: R1-numerics tiled kernel over flagged rows ----------------
#define RBM 128
#define RBN 128
#define RBK 32

__global__ void __launch_bounds__(256, 1)
rescue_kernel(const float* __restrict__ z, const float* __restrict__ emb,
              const float* __restrict__ sz, const float* __restrict__ se, int NE)
{
    extern __shared__ float smem[];
    float* sm_z  = smem;                 // [DIM][RBM] transposed
    float* sm_e  = smem + DIM * RBM;     // [RBK][RBN]
    float* run_d = sm_e + RBK * RBN;     // [RBM]
    int*   run_n = (int*)(run_d + RBM);  // [RBM]

    const int tid = threadIdx.x;
    const int tx = tid & 15;
    const int ty = tid >> 4;
    const int cnt = g_cnt;

    for (int tile = blockIdx.x; tile * RBM < cnt; tile += gridDim.x) {
        // transposed z load via indirection
        int r = tid >> 1;
        int half = tid & 1;
        int li_r = tile * RBM + r;
        int grow_r = g_list[li_r < cnt ? li_r : cnt - 1];
        {
            const float4* src = (const float4*)(z + (size_t)grow_r * DIM + half * 128);
#pragma unroll
            for (int qq = 0; qq < 32; qq++) {
                float4 v = src[qq];
                int k = half * 128 + qq * 4;
                sm_z[(k + 0) * RBM + r] = v.x;
                sm_z[(k + 1) * RBM + r] = v.y;
                sm_z[(k + 2) * RBM + r] = v.z;
                sm_z[(k + 3) * RBM + r] = v.w;
            }
        }
        if (tid < RBM) { run_d[tid] = FLT_MAX; run_n[tid] = 0; }

        float szr[8];
#pragma unroll
        for (int i = 0; i < 8; i++) {
            int li = tile * RBM + ty * 8 + i;
            szr[i] = __ldg(sz + g_list[li < cnt ? li : cnt - 1]);
        }
        __syncthreads();

        const int ec = tid >> 1;
        const int ekh = (tid & 1) * 16;

#pragma unroll 1
        for (int nbase = 0; nbase < NE; nbase += RBN) {
            ull acc2[8][4];
#pragma unroll
            for (int i = 0; i < 8; i++)
#pragma unroll
                for (int j = 0; j < 4; j++) acc2[i][j] = 0ull;

            float4 pf0, pf1, pf2, pf3;
            {
                const float4* src = (const float4*)(emb + (size_t)(nbase + ec) * DIM + ekh);
                pf0 = src[0]; pf1 = src[1]; pf2 = src[2]; pf3 = src[3];
            }

#pragma unroll 1
            for (int s = 0; s < DIM / RBK; s++) {
                __syncthreads();
                {
                    float* dst = sm_e + ec;
                    dst[(ekh + 0)  * RBN] = pf0.x; dst[(ekh + 1)  * RBN] = pf0.y;
                    dst[(ekh + 2)  * RBN] = pf0.z; dst[(ekh + 3)  * RBN] = pf0.w;
                    dst[(ekh + 4)  * RBN] = pf1.x; dst[(ekh + 5)  * RBN] = pf1.y;
                    dst[(ekh + 6)  * RBN] = pf1.z; dst[(ekh + 7)  * RBN] = pf1.w;
                    dst[(ekh + 8)  * RBN] = pf2.x; dst[(ekh + 9)  * RBN] = pf2.y;
                    dst[(ekh + 10) * RBN] = pf2.z; dst[(ekh + 11) * RBN] = pf2.w;
                    dst[(ekh + 12) * RBN] = pf3.x; dst[(ekh + 13) * RBN] = pf3.y;
                    dst[(ekh + 14) * RBN] = pf3.z; dst[(ekh + 15) * RBN] = pf3.w;
                }
                __syncthreads();
                if (s + 1 < DIM / RBK) {
                    const float4* src = (const float4*)(emb + (size_t)(nbase + ec) * DIM
                                                        + (s + 1) * RBK + ekh);
                    pf0 = src[0]; pf1 = src[1]; pf2 = src[2]; pf3 = src[3];
                }
                const float* zs = sm_z + (s * RBK) * RBM + ty * 8;
                const float* es = sm_e + tx * 8;
#pragma unroll 8
                for (int kk = 0; kk < RBK; kk++) {
                    float4 a0 = *(const float4*)(zs + kk * RBM);
                    float4 a1 = *(const float4*)(zs + kk * RBM + 4);
                    float4 b0 = *(const float4*)(es + kk * RBN);
                    float4 b1 = *(const float4*)(es + kk * RBN + 4);
                    ull bb0, bb1, bb2, bb3;
                    PACK2(bb0, b0.x, b0.y); PACK2(bb1, b0.z, b0.w);
                    PACK2(bb2, b1.x, b1.y); PACK2(bb3, b1.z, b1.w);
                    float av[8] = {a0.x, a0.y, a0.z, a0.w, a1.x, a1.y, a1.z, a1.w};
#pragma unroll
                    for (int i = 0; i < 8; i++) {
                        ull aa; PACK2(aa, av[i], av[i]);
                        FMA2(acc2[i][0], aa, bb0);
                        FMA2(acc2[i][1], aa, bb1);
                        FMA2(acc2[i][2], aa, bb2);
                        FMA2(acc2[i][3], aa, bb3);
                    }
                }
            }

            float4 se0 = *(const float4*)(se + nbase + tx * 8);
            float4 se1 = *(const float4*)(se + nbase + tx * 8 + 4);
            float sen[8] = {se0.x, se0.y, se0.z, se0.w, se1.x, se1.y, se1.z, se1.w};
#pragma unroll
            for (int i = 0; i < 8; i++) {
                float bdv = FLT_MAX; int bnv = 0;
#pragma unroll
                for (int j2 = 0; j2 < 4; j2++) {
                    unsigned plo_u, phi_u;
                    UNPACK2(plo_u, phi_u, acc2[i][j2]);
                    float plo = __uint_as_float(plo_u);
                    float phi = __uint_as_float(phi_u);
                    float t0 = __fadd_rn(szr[i], sen[2 * j2]);
                    float t1 = __fadd_rn(szr[i], sen[2 * j2 + 1]);
                    float dd0 = __fadd_rn(t0, __fmul_rn(-2.0f, plo));
                    float dd1 = __fadd_rn(t1, __fmul_rn(-2.0f, phi));
                    if (dd0 < bdv) { bdv = dd0; bnv = nbase + tx * 8 + 2 * j2; }
                    if (dd1 < bdv) { bdv = dd1; bnv = nbase + tx * 8 + 2 * j2 + 1; }
                }
#pragma unroll
                for (int off = 8; off; off >>= 1) {
                    float od = __shfl_down_sync(0xffffffffu, bdv, off, 16);
                    int   on = __shfl_down_sync(0xffffffffu, bnv, off, 16);
                    if (od < bdv || (od == bdv && on < bnv)) { bdv = od; bnv = on; }
                }
                if (tx == 0) {
                    int rr = ty * 8 + i;
                    if (bdv < run_d[rr]) { run_d[rr] = bdv; run_n[rr] = bnv; }
                }
            }
        }

        __syncthreads();
        if (tid < RBM) {
            int li = tile * RBM + tid;
            if (li < cnt) g_idx[g_list[li]] = run_n[tid];
        }
        __syncthreads();
    }
}

// ---------------- output gather ----------------
__global__ void gather_kernel(const float* __restrict__ emb, float* __restrict__ outp,
                              int B, int mode, long long idx_off)
{
    int w = (int)((blockIdx.x * blockDim.x + threadIdx.x) >> 5);
    int lane = threadIdx.x & 31;
    if (w >= B) return;
    int idx = g_idx[w];
    if (mode & 1) {
        const float4* src = (const float4*)(emb + (size_t)idx * DIM);
        float4* dst = (float4*)(outp + (size_t)w * DIM);
        dst[lane] = src[lane];
        dst[lane + 32] = src[lane + 32];
    }
    if ((mode & 2) && lane == 0) outp[idx_off + w] = (float)idx;
}

extern "C" void kernel_launch(void* const* d_in, const int* in_sizes, int n_in,
                              void* d_out, int out_size) {
    const float* z   = (const float*)d_in[0];
    const float* emb = (const float*)d_in[1];
    float* outp = (float*)d_out;

    int B  = in_sizes[0] / DIM;
    int NE = in_sizes[1] / DIM;

    float *sz_p, *se_p, *zhi_p, *zlo_p, *ehi_p, *elo_p;
    cudaGetSymbolAddress((void**)&sz_p,  g_sz);
    cudaGetSymbolAddress((void**)&se_p,  g_se);
    cudaGetSymbolAddress((void**)&zhi_p, g_zhi);
    cudaGetSymbolAddress((void**)&zlo_p, g_zlo);
    cudaGetSymbolAddress((void**)&ehi_p, g_ehi);
    cudaGetSymbolAddress((void**)&elo_p, g_elo);

    row_sumsq_kernel<<<(B + 7) / 8, 256>>>(z, sz_p, B);
    row_sumsq_kernel<<<(NE + 7) / 8, 256>>>(emb, se_p, NE);
    int nz4 = B * DIM / 4, ne4 = NE * DIM / 4;
    split_tf32_kernel<<<(nz4 + 255) / 256, 256>>>(z, zhi_p, zlo_p, nz4);
    split_tf32_kernel<<<(ne4 + 255) / 256, 256>>>(emb, ehi_p, elo_p, ne4);

    zero_cnt_kernel<<<1, 1>>>();

    cudaFuncSetAttribute(vq_mma_kernel, cudaFuncAttributeMaxDynamicSharedMemorySize, SMEM_REQ);
    vq_mma_kernel<<<B / TM, THREADS, SMEM_REQ>>>(zhi_p, zlo_p, ehi_p, elo_p, sz_p, se_p, NE);

    compact_kernel<<<(B + 255) / 256, 256>>>(B);

    size_t rs_smem = (size_t)(DIM * RBM + RBK * RBN + RBM) * sizeof(float) + RBM * sizeof(int);
    cudaFuncSetAttribute(rescue_kernel, cudaFuncAttributeMaxDynamicSharedMemorySize, (int)rs_smem);
    rescue_kernel<<<128, 256, rs_smem>>>(z, emb, sz_p, se_p, NE);

    long long zq_elems = (long long)B * DIM;
    int mode; long long idx_off;
    if ((long long)out_size >= zq_elems + B) { mode = 3; idx_off = zq_elems; }
    else if ((long long)out_size >= zq_elems) { mode = 1; idx_off = 0; }
    else { mode = 2; idx_off = 0; }

    gather_kernel<<<(B * 32 + 255) / 256, 256>>>(emb, outp, B, mode, idx_off);
}